// round 7
// baseline (speedup 1.0000x reference)
#include <cuda_runtime.h>
#include <cstdint>

// Problem constants
#define LL 2
#define BB 16
#define TT 512
#define HH 12
#define NL 4096   // (1+1)^12 leaves
#define NC 1000
#define NCHUNK 16 // token chunks per batch
#define TOKC 32   // tokens per chunk

// Scratch: [chunk][batch][leaf]  (4 MB)
__device__ float g_part[NCHUNK * BB * NL];

// ---- f32x2 helpers ---------------------------------------------------------
__device__ __forceinline__ unsigned long long pk2(float x, float y) {
    unsigned long long r;
    asm("mov.b64 %0, {%1, %2};" : "=l"(r) : "f"(x), "f"(y));
    return r;
}
__device__ __forceinline__ void fma2(unsigned long long& d,
                                     unsigned long long a,
                                     unsigned long long b) {
    asm("fma.rn.f32x2 %0, %1, %2, %0;" : "+l"(d) : "l"(a), "l"(b));
}
__device__ __forceinline__ void upk2(unsigned long long v, float& lo, float& hi) {
    asm("mov.b64 {%0, %1}, %2;" : "=f"(lo), "=f"(hi) : "l"(v));
}

// ---- cp.async helpers ------------------------------------------------------
__device__ __forceinline__ uint32_t smem_u32(const void* p) {
    uint32_t a;
    asm("{ .reg .u64 t; cvta.to.shared.u64 t, %1; cvt.u32.u64 %0, t; }"
        : "=r"(a) : "l"(p));
    return a;
}
__device__ __forceinline__ void cp_async16(uint32_t dst, const void* src, int sz) {
    asm volatile("cp.async.cg.shared.global [%0], [%1], 16, %2;"
                 :: "r"(dst), "l"(src), "r"(sz));
}
__device__ __forceinline__ void cp_commit() {
    asm volatile("cp.async.commit_group;");
}
template <int N> __device__ __forceinline__ void cp_wait() {
    asm volatile("cp.async.wait_group %0;" :: "n"(N));
}

// ---------------------------------------------------------------------------
// Kernel 1: per-(batch, token-chunk) partial mean-leaf vectors, disjoint STG.
// grid = B * NCHUNK = 256 blocks, 256 threads. Also zeroes `out`.
// ---------------------------------------------------------------------------
__global__ __launch_bounds__(256) void leaf_kernel(
    const float* __restrict__ x, const float* __restrict__ cuts,
    float* __restrict__ out)
{
    const int tid = threadIdx.x;
    const int gid = blockIdx.x * 256 + tid;    // 65536 >= 16000
    if (gid < BB * NC) out[gid] = 0.f;

    const int b     = blockIdx.x >> 4;
    const int chunk = blockIdx.x & 15;

    __shared__ float P[TOKC * 128];            // [tok][half*64 + u]  (16 KB)
    __shared__ float sx[TOKC * 12];
    __shared__ float sc[12];

    if (tid < 12) sc[tid] = cuts[tid];

    const float* xl = x + (size_t)(LL - 1) * BB * TT * HH
                        + ((size_t)b * TT + (size_t)chunk * TOKC) * HH;
    for (int i = tid; i < TOKC * 12; i += 256) sx[i] = xl[i];
    __syncthreads();

    // Phase A: factorized half-leaf products (8 contiguous outputs per task)
    {
        const int half = (tid >> 3) & 1;
        const int g    = tid & 7;
        const float* cr = sc + half * 6;
        const float c0 = cr[0], c1 = cr[1], c2 = cr[2];
        const float c3 = cr[3], c4 = cr[4], c5 = cr[5];
#pragma unroll
        for (int t2 = 0; t2 < 2; t2++) {
            const int tok = (tid >> 4) + t2 * 16;
            const float* xr = sx + tok * 12 + half * 6;
            const float x0 = xr[0], x1 = xr[1], x2 = xr[2];
            const float x3 = xr[3], x4 = xr[4], x5 = xr[5];
            const float F0 = (g & 4) ? fmaf(2.f, x0, -c0) : x0;
            const float F1 = (g & 2) ? fmaf(2.f, x1, -c1) : x1;
            const float F2 = (g & 1) ? fmaf(2.f, x2, -c2) : x2;
            const float p  = F0 * F1 * F2;
            const float b3 = fmaf(2.f, x3, -c3);
            const float a4 = x4, b4 = fmaf(2.f, x4, -c4);
            const float a5 = x5, b5 = fmaf(2.f, x5, -c5);
            const float m00 = a4 * a5, m01 = a4 * b5;
            const float m10 = b4 * a5, m11 = b4 * b5;
            const float q0 = p * x3, q1 = p * b3;
            float* dst = P + tok * 128 + half * 64 + g * 8;
            *(float4*)dst       = make_float4(q0 * m00, q0 * m01, q0 * m10, q0 * m11);
            *(float4*)(dst + 4) = make_float4(q1 * m00, q1 * m01, q1 * m10, q1 * m11);
        }
    }
    __syncthreads();

    // Phase B: rank-1 accumulation
    const int w = tid >> 5, lane = tid & 31;
    unsigned long long acc2[4][2];
#pragma unroll
    for (int p = 0; p < 4; p++) { acc2[p][0] = 0ull; acc2[p][1] = 0ull; }

#pragma unroll 4
    for (int tok = 0; tok < TOKC; tok++) {
        const float* Pr = P + tok * 128;
        const ulonglong2* ph = (const ulonglong2*)(Pr + 8 * w);
        const ulonglong2 h0 = ph[0];
        const ulonglong2 h1 = ph[1];
        const float plo0 = Pr[64 + lane];
        const float plo1 = Pr[64 + lane + 32];
        const unsigned long long pl0 = pk2(plo0, plo0);
        const unsigned long long pl1 = pk2(plo1, plo1);
        fma2(acc2[0][0], h0.x, pl0); fma2(acc2[0][1], h0.x, pl1);
        fma2(acc2[1][0], h0.y, pl0); fma2(acc2[1][1], h0.y, pl1);
        fma2(acc2[2][0], h1.x, pl0); fma2(acc2[2][1], h1.x, pl1);
        fma2(acc2[3][0], h1.y, pl0); fma2(acc2[3][1], h1.y, pl1);
    }

    const float s = 1.f / (float)TT;
    float* dst = g_part + ((size_t)(chunk * BB + b)) * NL;
#pragma unroll
    for (int p = 0; p < 4; p++) {
        float u0v0, u1v0, u0v1, u1v1;
        upk2(acc2[p][0], u0v0, u1v0);
        upk2(acc2[p][1], u0v1, u1v1);
        const int u0 = 8 * w + 2 * p;
        dst[u0 * 64 + lane]            = u0v0 * s;
        dst[u0 * 64 + lane + 32]       = u0v1 * s;
        dst[(u0 + 1) * 64 + lane]      = u1v0 * s;
        dst[(u0 + 1) * 64 + lane + 32] = u1v1 * s;
    }
}

// ---------------------------------------------------------------------------
// Kernel 2: out[16,1000] += avg[16,4096] @ score[4096,1000].
// grid = (32, 8), 256 threads. LCHUNK=128 rows, CTILE=128 cols.
// Rolling 4-stage cp.async pipeline (16 rows / 8 KB per stage) keeps loads
// continuously in flight; tail uses empty commit groups so wait<3> is uniform.
// Thread owns 1 column x 8 batches (tid>>7 selects batch half).
// ---------------------------------------------------------------------------
#define G_LCH  128
#define G_CT   128
#define SROWS  16
#define NSTAGE 4
#define NITER  (G_LCH / SROWS)   // 8

__global__ __launch_bounds__(256) void gemm_out_kernel(
    const float* __restrict__ score, float* __restrict__ out)
{
    __shared__ float sS[NSTAGE * SROWS * G_CT];  // 32 KB (4 slots x 16 rows)
    __shared__ float sA[G_LCH * 16];             // 8 KB [l][b]

    const int tid = threadIdx.x;
    const int l0  = blockIdx.x * G_LCH;
    const int c0  = blockIdx.y * G_CT;
    const uint32_t sS_base = smem_u32(sS);

    // Stage issue: stage s (rows l0+s*16 .. +16) into slot s&3.
    auto issue_stage = [&](int s) {
        const int slot = s & (NSTAGE - 1);
#pragma unroll
        for (int t = 0; t < 2; t++) {
            const int k  = tid + t * 256;          // 0..511 16B-chunk id
            const int r  = k >> 5;                 // row in stage 0..15
            const int cc = k & 31;                 // 16B chunk in row
            const int col = c0 + cc * 4;
            const char* src = (const char*)score
                + (size_t)(l0 + s * SROWS + r) * (NC * 4) + (size_t)col * 4;
            const uint32_t dst = sS_base
                + (uint32_t)(((slot * SROWS + r) * G_CT + cc * 4) * 4);
            const int sz = (col + 4 <= NC) ? 16 : 0;
            cp_async16(dst, src, sz);
        }
        cp_commit();
    };

    // Prologue: 4 stages in flight
#pragma unroll
    for (int s = 0; s < NSTAGE; s++) issue_stage(s);

    // Build sA by reducing the 16 L2-hot chunk partials (float4)
    for (int e = tid; e < 512; e += 256) {
        const int bb = e >> 5;            // batch 0..15
        const int lq = e & 31;            // leaf quad 0..31
        const float4* p = (const float4*)(g_part + (size_t)bb * NL + l0) + lq;
        float4 v = make_float4(0.f, 0.f, 0.f, 0.f);
#pragma unroll
        for (int ch = 0; ch < NCHUNK; ch++) {
            const float4 t = p[(size_t)ch * (BB * NL / 4)];
            v.x += t.x; v.y += t.y; v.z += t.z; v.w += t.w;
        }
        sA[(lq * 4 + 0) * 16 + bb] = v.x;
        sA[(lq * 4 + 1) * 16 + bb] = v.y;
        sA[(lq * 4 + 2) * 16 + bb] = v.z;
        sA[(lq * 4 + 3) * 16 + bb] = v.w;
    }

    unsigned long long acc[4];
#pragma unroll
    for (int p = 0; p < 4; p++) acc[p] = 0ull;

    const int ci    = tid & 127;          // column within tile
    const int bhalf = tid >> 7;           // batch half (0: b0-7, 1: b8-15)
    const int c     = c0 + ci;

    // Main loop: wait oldest stage, compute, refill freed slot (or dummy group)
    for (int it = 0; it < NITER; it++) {
        cp_wait<NSTAGE - 1>();
        __syncthreads();

        const int slot = it & (NSTAGE - 1);
        const float* sSrow = sS + slot * (SROWS * G_CT) + ci;
        const float* sArow = sA + (it * SROWS) * 16 + bhalf * 8;
#pragma unroll
        for (int r = 0; r < SROWS; r++) {
            const float sv = sSrow[r * G_CT];
            const unsigned long long ss = pk2(sv, sv);
            const ulonglong2 q = *(const ulonglong2*)(sArow + r * 16);
            const ulonglong2 q2v = *(const ulonglong2*)(sArow + r * 16 + 4);
            fma2(acc[0], ss, q.x);   fma2(acc[1], ss, q.y);
            fma2(acc[2], ss, q2v.x); fma2(acc[3], ss, q2v.y);
        }
        __syncthreads();

        if (it + NSTAGE < NITER) issue_stage(it + NSTAGE);
        else cp_commit();                 // empty group keeps wait<3> accounting
    }

    if (c < NC) {
#pragma unroll
        for (int p = 0; p < 4; p++) {
            float blo, bhi;
            upk2(acc[p], blo, bhi);
            const int bb = bhalf * 8 + 2 * p;
            atomicAdd(out + bb * NC + c,       blo);
            atomicAdd(out + (bb + 1) * NC + c, bhi);
        }
    }
}

// ---------------------------------------------------------------------------
extern "C" void kernel_launch(void* const* d_in, const int* in_sizes, int n_in,
                              void* d_out, int out_size)
{
    const float* x     = (const float*)d_in[0];  // (2,16,512,12)
    const float* cuts  = (const float*)d_in[1];  // (12,1)
    const float* score = (const float*)d_in[2];  // (4096,1000)
    float* out = (float*)d_out;                  // (16,1000)

    leaf_kernel<<<BB * NCHUNK, 256>>>(x, cuts, out);
    dim3 g3(NL / G_LCH, (NC + G_CT - 1) / G_CT);   // (32, 8)
    gemm_out_kernel<<<g3, 256>>>(score, out);
}

// round 8
// speedup vs baseline: 1.0017x; 1.0017x over previous
#include <cuda_runtime.h>
#include <cstdint>

// Problem constants
#define LL 2
#define BB 16
#define TT 512
#define HH 12
#define NL 4096   // (1+1)^12 leaves
#define NC 1000
#define NCHUNK 16 // token chunks per batch
#define TOKC 32   // tokens per chunk

// Scratch: [chunk][batch][leaf]  (4 MB)
__device__ float g_part[NCHUNK * BB * NL];

// ---- f32x2 helpers ---------------------------------------------------------
__device__ __forceinline__ unsigned long long pk2(float x, float y) {
    unsigned long long r;
    asm("mov.b64 %0, {%1, %2};" : "=l"(r) : "f"(x), "f"(y));
    return r;
}
__device__ __forceinline__ void fma2(unsigned long long& d,
                                     unsigned long long a,
                                     unsigned long long b) {
    asm("fma.rn.f32x2 %0, %1, %2, %0;" : "+l"(d) : "l"(a), "l"(b));
}
__device__ __forceinline__ void upk2(unsigned long long v, float& lo, float& hi) {
    asm("mov.b64 {%0, %1}, %2;" : "=f"(lo), "=f"(hi) : "l"(v));
}

// ---- cp.async helpers ------------------------------------------------------
__device__ __forceinline__ uint32_t smem_u32(const void* p) {
    uint32_t a;
    asm("{ .reg .u64 t; cvta.to.shared.u64 t, %1; cvt.u32.u64 %0, t; }"
        : "=r"(a) : "l"(p));
    return a;
}
__device__ __forceinline__ void cp_async16(uint32_t dst, const void* src, int sz) {
    asm volatile("cp.async.cg.shared.global [%0], [%1], 16, %2;"
                 :: "r"(dst), "l"(src), "r"(sz));
}
__device__ __forceinline__ void cp_commit() {
    asm volatile("cp.async.commit_group;");
}
template <int N> __device__ __forceinline__ void cp_wait() {
    asm volatile("cp.async.wait_group %0;" :: "n"(N));
}

// ---------------------------------------------------------------------------
// Kernel 1: per-(batch, token-chunk) partial mean-leaf vectors, disjoint STG.
// grid = B * NCHUNK = 256 blocks, 256 threads. Also zeroes `out`.
// ---------------------------------------------------------------------------
__global__ __launch_bounds__(256) void leaf_kernel(
    const float* __restrict__ x, const float* __restrict__ cuts,
    float* __restrict__ out)
{
    const int tid = threadIdx.x;
    const int gid = blockIdx.x * 256 + tid;    // 65536 >= 16000
    if (gid < BB * NC) out[gid] = 0.f;

    const int b     = blockIdx.x >> 4;
    const int chunk = blockIdx.x & 15;

    __shared__ float P[TOKC * 128];            // [tok][half*64 + u]  (16 KB)
    __shared__ float sx[TOKC * 12];
    __shared__ float sc[12];

    if (tid < 12) sc[tid] = cuts[tid];

    const float* xl = x + (size_t)(LL - 1) * BB * TT * HH
                        + ((size_t)b * TT + (size_t)chunk * TOKC) * HH;
    for (int i = tid; i < TOKC * 12; i += 256) sx[i] = xl[i];
    __syncthreads();

    // Phase A: factorized half-leaf products (8 contiguous outputs per task)
    {
        const int half = (tid >> 3) & 1;
        const int g    = tid & 7;
        const float* cr = sc + half * 6;
        const float c0 = cr[0], c1 = cr[1], c2 = cr[2];
        const float c3 = cr[3], c4 = cr[4], c5 = cr[5];
#pragma unroll
        for (int t2 = 0; t2 < 2; t2++) {
            const int tok = (tid >> 4) + t2 * 16;
            const float* xr = sx + tok * 12 + half * 6;
            const float x0 = xr[0], x1 = xr[1], x2 = xr[2];
            const float x3 = xr[3], x4 = xr[4], x5 = xr[5];
            const float F0 = (g & 4) ? fmaf(2.f, x0, -c0) : x0;
            const float F1 = (g & 2) ? fmaf(2.f, x1, -c1) : x1;
            const float F2 = (g & 1) ? fmaf(2.f, x2, -c2) : x2;
            const float p  = F0 * F1 * F2;
            const float b3 = fmaf(2.f, x3, -c3);
            const float a4 = x4, b4 = fmaf(2.f, x4, -c4);
            const float a5 = x5, b5 = fmaf(2.f, x5, -c5);
            const float m00 = a4 * a5, m01 = a4 * b5;
            const float m10 = b4 * a5, m11 = b4 * b5;
            const float q0 = p * x3, q1 = p * b3;
            float* dst = P + tok * 128 + half * 64 + g * 8;
            *(float4*)dst       = make_float4(q0 * m00, q0 * m01, q0 * m10, q0 * m11);
            *(float4*)(dst + 4) = make_float4(q1 * m00, q1 * m01, q1 * m10, q1 * m11);
        }
    }
    __syncthreads();

    // Phase B: rank-1 accumulation
    const int w = tid >> 5, lane = tid & 31;
    unsigned long long acc2[4][2];
#pragma unroll
    for (int p = 0; p < 4; p++) { acc2[p][0] = 0ull; acc2[p][1] = 0ull; }

#pragma unroll 4
    for (int tok = 0; tok < TOKC; tok++) {
        const float* Pr = P + tok * 128;
        const ulonglong2* ph = (const ulonglong2*)(Pr + 8 * w);
        const ulonglong2 h0 = ph[0];
        const ulonglong2 h1 = ph[1];
        const float plo0 = Pr[64 + lane];
        const float plo1 = Pr[64 + lane + 32];
        const unsigned long long pl0 = pk2(plo0, plo0);
        const unsigned long long pl1 = pk2(plo1, plo1);
        fma2(acc2[0][0], h0.x, pl0); fma2(acc2[0][1], h0.x, pl1);
        fma2(acc2[1][0], h0.y, pl0); fma2(acc2[1][1], h0.y, pl1);
        fma2(acc2[2][0], h1.x, pl0); fma2(acc2[2][1], h1.x, pl1);
        fma2(acc2[3][0], h1.y, pl0); fma2(acc2[3][1], h1.y, pl1);
    }

    const float s = 1.f / (float)TT;
    float* dst = g_part + ((size_t)(chunk * BB + b)) * NL;
#pragma unroll
    for (int p = 0; p < 4; p++) {
        float u0v0, u1v0, u0v1, u1v1;
        upk2(acc2[p][0], u0v0, u1v0);
        upk2(acc2[p][1], u0v1, u1v1);
        const int u0 = 8 * w + 2 * p;
        dst[u0 * 64 + lane]            = u0v0 * s;
        dst[u0 * 64 + lane + 32]       = u0v1 * s;
        dst[(u0 + 1) * 64 + lane]      = u1v0 * s;
        dst[(u0 + 1) * 64 + lane + 32] = u1v1 * s;
    }
}

// ---------------------------------------------------------------------------
// Kernel 2: out[16,1000] += avg[16,4096] @ score[4096,1000].
// grid = (64, 8) = 512 CTAs, 256 threads (8 warps): occupancy ~43%.
// CTA tile: 64 rows x 128 cols; thread = (col, batch-half) with 4 f32x2 accs.
// Rolling 3-stage cp.async pipeline (16 rows / 8 KB per stage).
// ---------------------------------------------------------------------------
#define G_LCH  64
#define G_CT   128
#define SROWS  16
#define NSTAGE 3
#define NITER  (G_LCH / SROWS)   // 4

__global__ __launch_bounds__(256) void gemm_out_kernel(
    const float* __restrict__ score, float* __restrict__ out)
{
    __shared__ float sS[NSTAGE * SROWS * G_CT];  // 24 KB (3 slots x 16 rows)
    __shared__ float sA[G_LCH * 16];             // 4 KB [l][b]

    const int tid = threadIdx.x;
    const int l0  = blockIdx.x * G_LCH;
    const int c0  = blockIdx.y * G_CT;
    const uint32_t sS_base = smem_u32(sS);

    // Stage issue: stage s (rows l0+s*16 .. +16) into slot s%3.
    auto issue_stage = [&](int s) {
        const int slot = s % NSTAGE;
#pragma unroll
        for (int t = 0; t < 2; t++) {
            const int k  = tid + t * 256;          // 0..511 16B-chunk id
            const int r  = k >> 5;                 // row in stage 0..15
            const int cc = k & 31;                 // 16B chunk in row
            const int col = c0 + cc * 4;
            const char* src = (const char*)score
                + (size_t)(l0 + s * SROWS + r) * (NC * 4) + (size_t)col * 4;
            const uint32_t dst = sS_base
                + (uint32_t)(((slot * SROWS + r) * G_CT + cc * 4) * 4);
            const int sz = (col + 4 <= NC) ? 16 : 0;
            cp_async16(dst, src, sz);
        }
        cp_commit();
    };

    // Prologue: 3 stages in flight
#pragma unroll
    for (int s = 0; s < NSTAGE; s++) issue_stage(s);

    // Build sA by reducing the 16 L2-hot chunk partials (float4):
    // 256 tasks = 16 batches x 16 leaf-quads, one per thread.
    {
        const int bb = tid >> 4;          // batch 0..15
        const int lq = tid & 15;          // leaf quad 0..15
        const float4* p = (const float4*)(g_part + (size_t)bb * NL + l0) + lq;
        float4 v = make_float4(0.f, 0.f, 0.f, 0.f);
#pragma unroll
        for (int ch = 0; ch < NCHUNK; ch++) {
            const float4 t = p[(size_t)ch * (BB * NL / 4)];
            v.x += t.x; v.y += t.y; v.z += t.z; v.w += t.w;
        }
        sA[(lq * 4 + 0) * 16 + bb] = v.x;
        sA[(lq * 4 + 1) * 16 + bb] = v.y;
        sA[(lq * 4 + 2) * 16 + bb] = v.z;
        sA[(lq * 4 + 3) * 16 + bb] = v.w;
    }

    unsigned long long acc[4];
#pragma unroll
    for (int p = 0; p < 4; p++) acc[p] = 0ull;

    const int ci    = tid & 127;          // column within tile
    const int bhalf = tid >> 7;           // batch half (0: b0-7, 1: b8-15)
    const int c     = c0 + ci;

    // Main loop: wait oldest stage, compute, refill freed slot (or dummy group)
#pragma unroll
    for (int it = 0; it < NITER; it++) {
        cp_wait<NSTAGE - 1>();
        __syncthreads();

        const int slot = it % NSTAGE;
        const float* sSrow = sS + slot * (SROWS * G_CT) + ci;
        const float* sArow = sA + (it * SROWS) * 16 + bhalf * 8;
#pragma unroll
        for (int r = 0; r < SROWS; r++) {
            const float sv = sSrow[r * G_CT];
            const unsigned long long ss = pk2(sv, sv);
            const ulonglong2 q  = *(const ulonglong2*)(sArow + r * 16);
            const ulonglong2 q2 = *(const ulonglong2*)(sArow + r * 16 + 4);
            fma2(acc[0], ss, q.x);  fma2(acc[1], ss, q.y);
            fma2(acc[2], ss, q2.x); fma2(acc[3], ss, q2.y);
        }
        __syncthreads();

        if (it + NSTAGE < NITER) issue_stage(it + NSTAGE);
        else cp_commit();                 // empty group keeps wait<2> accounting
    }

    if (c < NC) {
#pragma unroll
        for (int p = 0; p < 4; p++) {
            float blo, bhi;
            upk2(acc[p], blo, bhi);
            const int bb = bhalf * 8 + 2 * p;
            atomicAdd(out + bb * NC + c,       blo);
            atomicAdd(out + (bb + 1) * NC + c, bhi);
        }
    }
}

// ---------------------------------------------------------------------------
extern "C" void kernel_launch(void* const* d_in, const int* in_sizes, int n_in,
                              void* d_out, int out_size)
{
    const float* x     = (const float*)d_in[0];  // (2,16,512,12)
    const float* cuts  = (const float*)d_in[1];  // (12,1)
    const float* score = (const float*)d_in[2];  // (4096,1000)
    float* out = (float*)d_out;                  // (16,1000)

    leaf_kernel<<<BB * NCHUNK, 256>>>(x, cuts, out);
    dim3 g3(NL / G_LCH, (NC + G_CT - 1) / G_CT);   // (64, 8)
    gemm_out_kernel<<<g3, 256>>>(score, out);
}